// round 6
// baseline (speedup 1.0000x reference)
#include <cuda_runtime.h>

#define NBLK 128
#define NTHR 256
#define LDS_ 132   // padded smem row stride; 132 % 32 == 4 -> float4 row-per-lane reads conflict-free
#define LDK_ 68    // padded K=64 stride; 68 % 32 == 4 -> same property
typedef unsigned long long u64;

// Scratch (allocation-free rule: __device__ globals)
__device__ float g_h0[512 * 128];     // x @ fp_W + fp_b
__device__ float g_opWt[128 * 512];   // op_W transposed: [n][k]
__device__ float g_part[7 * 16 * 4096]; // t partials: [c-1][m-group][32*128]
__device__ unsigned g_flag0[NBLK];    // barrier flags (epoch-valued; never reset)
__device__ unsigned g_done[16];       // per-m-group arrival counters (reset by reducer)
__device__ unsigned g_epoch;          // bumped once per launch by block 0 at the end

__device__ __forceinline__ u64 ffma2(u64 a, u64 b, u64 c) {
    u64 d;
    asm("fma.rn.f32x2 %0, %1, %2, %3;" : "=l"(d) : "l"(a), "l"(b), "l"(c));
    return d;
}
__device__ __forceinline__ float f2lo(u64 v) { return __uint_as_float((unsigned)v); }
__device__ __forceinline__ float f2hi(u64 v) { return __uint_as_float((unsigned)(v >> 32)); }

// Warp tile: 4 m-rows (broadcast A) x 64 n (lane, lane+32) over one K=128 chunk.
__device__ __forceinline__ void wtile4(const float* __restrict__ As,
                                       const float* __restrict__ Bs,
                                       int lane, u64 acc[4][2])
{
    #pragma unroll 4
    for (int k4 = 0; k4 < 32; k4++) {
        ulonglong2 b0 = *(const ulonglong2*)(Bs + (size_t)lane        * LDS_ + k4 * 4);
        ulonglong2 b1 = *(const ulonglong2*)(Bs + (size_t)(lane + 32) * LDS_ + k4 * 4);
        #pragma unroll
        for (int i = 0; i < 4; i++) {
            ulonglong2 a = *(const ulonglong2*)(As + (size_t)i * LDS_ + k4 * 4);
            acc[i][0] = ffma2(a.x, b0.x, acc[i][0]);
            acc[i][0] = ffma2(a.y, b0.y, acc[i][0]);
            acc[i][1] = ffma2(a.x, b1.x, acc[i][1]);
            acc[i][1] = ffma2(a.y, b1.y, acc[i][1]);
        }
    }
}

__global__ void __launch_bounds__(NTHR, 1)
fused_kernel(const float* __restrict__ x,   const float* __restrict__ mask,
             const float* __restrict__ emb, const float* __restrict__ gatW,
             const float* __restrict__ fpW, const float* __restrict__ fpb,
             const float* __restrict__ opW, const float* __restrict__ opb,
             const int*   __restrict__ kp,  float* __restrict__ out)
{
    extern __shared__ float sm[];
    const int blk = blockIdx.x, t = threadIdx.x, lane = t & 31, w = t >> 5;
    const unsigned E = *(volatile unsigned*)&g_epoch;   // stable: bumped only at end of prior launch

    // ═ Phase 0: adj 2-row (0..47) ∥ adj 1-row (48..79) ∥ h0 (80..111) ∥ opWt (112..127)
    if (blk < 48) {
        // rows 2blk, 2blk+1 (lower index wins ties) — identical math to passing rounds
        float* es    = sm;                 // 128 x LDS_
        float* s_n2  = sm + 128 * LDS_;    // 128
        float* s_sim = s_n2 + 128;         // 2 x 128
        #pragma unroll
        for (int i = 0; i < 16; i++) {
            int idx = t + i * 256; int r = idx >> 5, c4 = idx & 31;
            *(float4*)(es + r * LDS_ + c4 * 4) =
                *(const float4*)(emb + (size_t)r * 128 + c4 * 4);
        }
        __syncthreads();
        const int rr = t >> 7, j = t & 127;
        const int irow = blk * 2 + rr;
        const float* ei = es + irow * LDS_;
        const float* ej = es + j * LDS_;
        float dij = 0.f, nj = 0.f;
        #pragma unroll 8
        for (int f4 = 0; f4 < 32; f4++) {
            float4 b = *(const float4*)(ej + f4 * 4);
            float4 a = *(const float4*)(ei + f4 * 4);
            dij += a.x * b.x + a.y * b.y + a.z * b.z + a.w * b.w;
            nj  += b.x * b.x + b.y * b.y + b.z * b.z + b.w * b.w;
        }
        if (rr == 0) s_n2[j] = nj;
        __syncthreads();
        float sim = dij / (sqrtf(s_n2[irow]) * sqrtf(nj));
        s_sim[rr * 128 + j] = sim;
        __syncthreads();
        const float4* S = (const float4*)(s_sim + rr * 128);
        int cnt = 0;
        #pragma unroll 8
        for (int q = 0; q < 32; q++) {
            float4 a = S[q];
            int base = q * 4;
            cnt += (a.x > sim) || (a.x == sim && base + 0 < j);
            cnt += (a.y > sim) || (a.y == sim && base + 1 < j);
            cnt += (a.z > sim) || (a.z == sim && base + 2 < j);
            cnt += (a.w > sim) || (a.w == sim && base + 3 < j);
        }
        out[65536 + irow * 128 + j] = (cnt < kp[0]) ? 1.0f : 0.0f;
    } else if (blk < 80) {
        // single row i = 96 + (blk-48); dot and rank split across thread halves
        float* es    = sm;                 // 128 x LDS_
        float* s_pn  = sm + 128 * LDS_;    // 2 x 128 partial norms
        float* s_pd  = s_pn + 256;         // 2 x 128 partial dots
        float* s_sim = s_pd + 256;         // 128
        int*   s_cnt = (int*)(s_sim + 128);// 2 x 128
        const int i = 96 + (blk - 48);
        #pragma unroll
        for (int q = 0; q < 16; q++) {
            int idx = t + q * 256; int r = idx >> 5, c4 = idx & 31;
            *(float4*)(es + r * LDS_ + c4 * 4) =
                *(const float4*)(emb + (size_t)r * 128 + c4 * 4);
        }
        __syncthreads();
        const int j = t & 127, half = t >> 7;
        const float* ei = es + i * LDS_;
        const float* ej = es + j * LDS_;
        float d = 0.f, nn = 0.f;
        #pragma unroll 8
        for (int q = 0; q < 16; q++) {
            int f4 = half * 16 + q;
            float4 b = *(const float4*)(ej + f4 * 4);
            float4 a = *(const float4*)(ei + f4 * 4);
            d  += a.x * b.x + a.y * b.y + a.z * b.z + a.w * b.w;
            nn += b.x * b.x + b.y * b.y + b.z * b.z + b.w * b.w;
        }
        s_pn[half * 128 + j] = nn;
        s_pd[half * 128 + j] = d;
        __syncthreads();
        if (half == 0) {
            float njf = s_pn[j] + s_pn[128 + j];
            s_pn[j] = njf;                 // reads of {j,128+j} done by all half0 first? safe: each j touches only its own slots
        }
        __syncthreads();
        if (half == 0) {
            float dij = s_pd[j] + s_pd[128 + j];
            s_sim[j] = dij / (sqrtf(s_pn[i]) * sqrtf(s_pn[j]));
        }
        __syncthreads();
        {
            float sim = s_sim[j];
            const float4* S = (const float4*)(s_sim + half * 64);
            int cnt = 0;
            #pragma unroll 8
            for (int q = 0; q < 16; q++) {
                float4 a = S[q];
                int base = half * 64 + q * 4;
                cnt += (a.x > sim) || (a.x == sim && base + 0 < j);
                cnt += (a.y > sim) || (a.y == sim && base + 1 < j);
                cnt += (a.z > sim) || (a.z == sim && base + 2 < j);
                cnt += (a.w > sim) || (a.w == sim && base + 3 < j);
            }
            s_cnt[half * 128 + j] = cnt;
        }
        __syncthreads();
        if (half == 0) {
            int c = s_cnt[j] + s_cnt[128 + j];
            out[65536 + i * 128 + j] = (c < kp[0]) ? 1.0f : 0.0f;
        }
    } else if (blk < 112) {
        // h0 tile [32 x 64]: h0 = x @ fp_W + fp_b, K=128
        int tt = blk - 80;
        int m0 = (tt >> 1) * 32, n0 = (tt & 1) * 64;
        float* As = sm;               // 32 x LDS_
        float* Bs = sm + 32 * LDS_;   // 64 x LDS_  (row = n_local, col = k)
        #pragma unroll
        for (int i = 0; i < 4; i++) {
            int idx = t + i * 256; int r = idx >> 5, c4 = idx & 31;
            *(float4*)(As + r * LDS_ + c4 * 4) =
                *(const float4*)(x + (size_t)(m0 + r) * 128 + c4 * 4);
        }
        {
            int kk = t & 127, half = t >> 7;
            #pragma unroll
            for (int p4 = 0; p4 < 8; p4++) {
                float4 v = *(const float4*)(fpW + (size_t)kk * 128 + n0 + (half * 8 + p4) * 4);
                Bs[((half * 8 + p4) * 4 + 0) * LDS_ + kk] = v.x;
                Bs[((half * 8 + p4) * 4 + 1) * LDS_ + kk] = v.y;
                Bs[((half * 8 + p4) * 4 + 2) * LDS_ + kk] = v.z;
                Bs[((half * 8 + p4) * 4 + 3) * LDS_ + kk] = v.w;
            }
        }
        __syncthreads();
        u64 acc[4][2];
        #pragma unroll
        for (int i = 0; i < 4; i++) { acc[i][0] = 0ull; acc[i][1] = 0ull; }
        wtile4(As + (size_t)(w * 4) * LDS_, Bs, lane, acc);
        #pragma unroll
        for (int i = 0; i < 4; i++) {
            int m = m0 + w * 4 + i;
            #pragma unroll
            for (int j = 0; j < 2; j++) {
                int n = n0 + lane + 32 * j;
                g_h0[(size_t)m * 128 + n] = f2lo(acc[i][j]) + f2hi(acc[i][j]) + fpb[n];
            }
        }
    } else {
        // opW transpose: k-slice [(blk-112)*32, +32); thread = (n, half)
        int k0 = (blk - 112) * 32;
        int n = t & 127, half = t >> 7;
        float v[16];
        #pragma unroll
        for (int kk = 0; kk < 16; kk++)
            v[kk] = opW[(size_t)(k0 + half * 16 + kk) * 128 + n];
        #pragma unroll
        for (int q = 0; q < 4; q++)
            *(float4*)(g_opWt + (size_t)n * 512 + k0 + half * 16 + q * 4) =
                make_float4(v[q * 4], v[q * 4 + 1], v[q * 4 + 2], v[q * 4 + 3]);
    }

    // ═ Flag barrier (single global sync; epoch-valued, no resets) ═══════════
    __threadfence();
    __syncthreads();
    if (t == 0) *(volatile unsigned*)&g_flag0[blk] = E + 1u;
    if (t < NBLK) {
        while (*(volatile unsigned*)&g_flag0[t] < E + 1u) { }
        __threadfence();
    }
    __syncthreads();

    // ═ Phase 1: block (m0g, c): r-chunk [32 x 64] (K=128) + t-partial (K=64) ═
    {
        const int m0g = blk >> 3, c = blk & 7;
        const int m0 = m0g * 32, c0 = c * 64;
        float* h0s = sm;                    // 32 x LDS_
        float* Bs  = sm + 32 * LDS_;        // 64 x LDS_ (gatW chunk, K-major rows)
        float* rrs = sm + 96 * LDS_;        // 32 x LDK_
        float* oWs = rrs + 32 * LDK_;       // 128 x LDK_
        float* tred = Bs;                   // reducer alias (32 x LDS_)

        #pragma unroll
        for (int i = 0; i < 4; i++) {
            int idx = t + i * 256; int r = idx >> 5, c4 = idx & 31;
            *(float4*)(h0s + r * LDS_ + c4 * 4) =
                *(const float4*)(g_h0 + (size_t)(m0 + r) * 128 + c4 * 4);
        }
        #pragma unroll
        for (int i = 0; i < 8; i++) {
            int idx = t + i * 256; int r = idx >> 5, c4 = idx & 31;
            *(float4*)(Bs + r * LDS_ + c4 * 4) =
                *(const float4*)(gatW + (size_t)(c0 + r) * 128 + c4 * 4);
        }
        {
            int n = t & 127, half = t >> 7;
            #pragma unroll
            for (int q4 = 0; q4 < 8; q4++)
                *(float4*)(oWs + (size_t)n * LDK_ + half * 32 + q4 * 4) =
                    *(const float4*)(g_opWt + (size_t)n * 512 + c0 + half * 32 + q4 * 4);
        }
        __syncthreads();

        u64 acc[4][2];
        #pragma unroll
        for (int i = 0; i < 4; i++) { acc[i][0] = 0ull; acc[i][1] = 0ull; }
        wtile4(h0s + (size_t)(w * 4) * LDS_, Bs, lane, acc);
        #pragma unroll
        for (int i = 0; i < 4; i++)
            #pragma unroll
            for (int j = 0; j < 2; j++)
                rrs[(w * 4 + i) * LDK_ + lane + 32 * j] =
                    fmaxf(f2lo(acc[i][j]) + f2hi(acc[i][j]), 0.0f);
        __syncthreads();

        // t-partial [4m x 128n], K = 64 (this chunk's c's)
        u64 a2[4][4];
        #pragma unroll
        for (int i = 0; i < 4; i++)
            #pragma unroll
            for (int j = 0; j < 4; j++) a2[i][j] = 0ull;
        #pragma unroll 4
        for (int k4 = 0; k4 < 16; k4++) {
            ulonglong2 b[4];
            #pragma unroll
            for (int j = 0; j < 4; j++)
                b[j] = *(const ulonglong2*)(oWs + (size_t)(lane + 32 * j) * LDK_ + k4 * 4);
            #pragma unroll
            for (int i = 0; i < 4; i++) {
                ulonglong2 a = *(const ulonglong2*)(rrs + (size_t)(w * 4 + i) * LDK_ + k4 * 4);
                #pragma unroll
                for (int j = 0; j < 4; j++) {
                    a2[i][j] = ffma2(a.x, b[j].x, a2[i][j]);
                    a2[i][j] = ffma2(a.y, b[j].y, a2[i][j]);
                }
            }
        }

        if (c != 0) {
            float* dst = g_part + (size_t)((c - 1) * 16 + m0g) * 4096;
            #pragma unroll
            for (int i = 0; i < 4; i++)
                #pragma unroll
                for (int j = 0; j < 4; j++)
                    dst[(w * 4 + i) * 128 + lane + 32 * j] =
                        f2lo(a2[i][j]) + f2hi(a2[i][j]);
            __threadfence();
            __syncthreads();
            if (t == 0) atomicAdd(&g_done[m0g], 1u);
        } else {
            #pragma unroll
            for (int i = 0; i < 4; i++)
                #pragma unroll
                for (int j = 0; j < 4; j++)
                    tred[(w * 4 + i) * LDS_ + lane + 32 * j] =
                        f2lo(a2[i][j]) + f2hi(a2[i][j]);
            __syncthreads();
            if (t == 0) {
                while (*(volatile unsigned*)&g_done[m0g] < 7u) { }
                __threadfence();
            }
            __syncthreads();
            // epilogue: thread covers floats [t*16, t*16+16) of the 32x128 tile
            const int m = t >> 3, nb = (t & 7) * 16;
            float4 v[4];
            #pragma unroll
            for (int q = 0; q < 4; q++)
                v[q] = *(const float4*)(tred + m * LDS_ + nb + q * 4);
            #pragma unroll
            for (int cc = 0; cc < 7; cc++) {
                const float* src = g_part + (size_t)(cc * 16 + m0g) * 4096 + m * 128 + nb;
                #pragma unroll
                for (int q = 0; q < 4; q++) {
                    float4 p = *(const float4*)(src + q * 4);
                    v[q].x += p.x; v[q].y += p.y; v[q].z += p.z; v[q].w += p.w;
                }
            }
            size_t gi = (size_t)(m0 + m) * 128 + nb;
            #pragma unroll
            for (int q = 0; q < 4; q++) {
                float4 bq = *(const float4*)(opb + nb + q * 4);
                float4 xv = *(const float4*)(x + gi + q * 4);
                float4 mv = *(const float4*)(mask + gi + q * 4);
                float4 o;
                o.x = xv.x * (1.0f - mv.x) + (v[q].x + bq.x) * mv.x;
                o.y = xv.y * (1.0f - mv.y) + (v[q].y + bq.y) * mv.y;
                o.z = xv.z * (1.0f - mv.z) + (v[q].z + bq.z) * mv.z;
                o.w = xv.w * (1.0f - mv.w) + (v[q].w + bq.w) * mv.w;
                *(float4*)(out + gi + q * 4) = o;
            }
            if (t == 0) g_done[m0g] = 0;   // reset for next launch
        }
    }

    if (blk == 0 && t == 0)
        *(volatile unsigned*)&g_epoch = E + 1u;   // after block 0 finished everything
}

extern "C" void kernel_launch(void* const* d_in, const int* in_sizes, int n_in,
                              void* d_out, int out_size)
{
    const float* x    = (const float*)d_in[0];
    const float* mask = (const float*)d_in[1];
    const float* emb  = (const float*)d_in[2];
    const float* gatW = (const float*)d_in[3];
    // d_in[4] = gat_a: provably unused (softmax over constant logits -> adj/k; rows sum to 1)
    const float* fpW  = (const float*)d_in[5];
    const float* fpb  = (const float*)d_in[6];
    const float* opW  = (const float*)d_in[7];
    const float* opb  = (const float*)d_in[8];
    const int*   kp   = (const int*)d_in[9];
    float* out = (float*)d_out;

    // 96*LDS_ + 160*LDK_ floats = 23552 floats = 94208 B (covers all phase layouts)
    const int SMEM = (96 * LDS_ + 160 * LDK_) * 4;
    cudaFuncSetAttribute(fused_kernel, cudaFuncAttributeMaxDynamicSharedMemorySize, SMEM);
    fused_kernel<<<NBLK, NTHR, SMEM>>>(x, mask, emb, gatW, fpW, fpb, opW, opb, kp, out);
}

// round 7
// speedup vs baseline: 1.0817x; 1.0817x over previous
#include <cuda_runtime.h>

#define NBLK 128
#define NTHR 256
#define LDS_ 132   // padded smem row stride; 132 % 32 == 4 -> float4 row-per-lane reads conflict-free
typedef unsigned long long u64;

// Scratch (allocation-free rule: __device__ globals)
__device__ float g_h0[512 * 128];    // x @ fp_W + fp_b
__device__ float g_r[512 * 512];     // relu(h0 @ gat_W^T)
__device__ float g_opWt[128 * 512];  // op_W transposed: [n][k]
__device__ unsigned g_c_h0  = 0;     // h0 arrivals   (monotonic; target 32*(E+1))
__device__ unsigned g_c_opw = 0;     // opWt arrivals (monotonic; target 16*(E+1))
__device__ unsigned g_flagr[NBLK];   // r-tile flags  (epoch-valued, never reset)
__device__ unsigned g_epoch = 0;     // bumped once per launch by block 0 at the end

__device__ __forceinline__ u64 ffma2(u64 a, u64 b, u64 c) {
    u64 d;
    asm("fma.rn.f32x2 %0, %1, %2, %3;" : "=l"(d) : "l"(a), "l"(b), "l"(c));
    return d;
}
__device__ __forceinline__ float f2lo(u64 v) { return __uint_as_float((unsigned)v); }
__device__ __forceinline__ float f2hi(u64 v) { return __uint_as_float((unsigned)(v >> 32)); }

// Warp tile: 4 m-rows (broadcast A) x 64 n (lane, lane+32) over one K=128 chunk.
__device__ __forceinline__ void wtile4(const float* __restrict__ As,
                                       const float* __restrict__ Bs,
                                       int lane, u64 acc[4][2])
{
    #pragma unroll 4
    for (int k4 = 0; k4 < 32; k4++) {
        ulonglong2 b0 = *(const ulonglong2*)(Bs + (size_t)lane        * LDS_ + k4 * 4);
        ulonglong2 b1 = *(const ulonglong2*)(Bs + (size_t)(lane + 32) * LDS_ + k4 * 4);
        #pragma unroll
        for (int i = 0; i < 4; i++) {
            ulonglong2 a = *(const ulonglong2*)(As + (size_t)i * LDS_ + k4 * 4);
            acc[i][0] = ffma2(a.x, b0.x, acc[i][0]);
            acc[i][0] = ffma2(a.y, b0.y, acc[i][0]);
            acc[i][1] = ffma2(a.x, b1.x, acc[i][1]);
            acc[i][1] = ffma2(a.y, b1.y, acc[i][1]);
        }
    }
}

__global__ void __launch_bounds__(NTHR, 1)
fused_kernel(const float* __restrict__ x,   const float* __restrict__ mask,
             const float* __restrict__ emb, const float* __restrict__ gatW,
             const float* __restrict__ fpW, const float* __restrict__ fpb,
             const float* __restrict__ opW, const float* __restrict__ opb,
             const int*   __restrict__ kp,  float* __restrict__ out)
{
    extern __shared__ float sm[];
    const int blk = blockIdx.x, t = threadIdx.x, lane = t & 31, w = t >> 5;
    const unsigned E = *(volatile unsigned*)&g_epoch;

    // ═ Phase 0: adj 2-row (0..47) ∥ adj 1-row (48..79) ∥ h0 (80..111) ∥ opWt (112..127)
    if (blk < 48) {
        float* es    = sm;                 // 128 x LDS_
        float* s_n2  = sm + 128 * LDS_;    // 128
        float* s_sim = s_n2 + 128;         // 2 x 128
        #pragma unroll
        for (int i = 0; i < 16; i++) {
            int idx = t + i * 256; int r = idx >> 5, c4 = idx & 31;
            *(float4*)(es + r * LDS_ + c4 * 4) =
                *(const float4*)(emb + (size_t)r * 128 + c4 * 4);
        }
        __syncthreads();
        const int rr = t >> 7, j = t & 127;
        const int irow = blk * 2 + rr;
        const float* ei = es + irow * LDS_;
        const float* ej = es + j * LDS_;
        float dij = 0.f, nj = 0.f;
        #pragma unroll 8
        for (int f4 = 0; f4 < 32; f4++) {
            float4 b = *(const float4*)(ej + f4 * 4);
            float4 a = *(const float4*)(ei + f4 * 4);
            dij += a.x * b.x + a.y * b.y + a.z * b.z + a.w * b.w;
            nj  += b.x * b.x + b.y * b.y + b.z * b.z + b.w * b.w;
        }
        if (rr == 0) s_n2[j] = nj;
        __syncthreads();
        float sim = dij / (sqrtf(s_n2[irow]) * sqrtf(nj));
        s_sim[rr * 128 + j] = sim;
        __syncthreads();
        const float4* S = (const float4*)(s_sim + rr * 128);
        int cnt = 0;
        #pragma unroll 8
        for (int q = 0; q < 32; q++) {
            float4 a = S[q];
            int base = q * 4;
            cnt += (a.x > sim) || (a.x == sim && base + 0 < j);
            cnt += (a.y > sim) || (a.y == sim && base + 1 < j);
            cnt += (a.z > sim) || (a.z == sim && base + 2 < j);
            cnt += (a.w > sim) || (a.w == sim && base + 3 < j);
        }
        out[65536 + irow * 128 + j] = (cnt < kp[0]) ? 1.0f : 0.0f;
    } else if (blk < 80) {
        // single row i = 96 + (blk-48); dot and rank split across thread halves
        float* es    = sm;                 // 128 x LDS_
        float* s_pn  = sm + 128 * LDS_;    // 2 x 128
        float* s_pd  = s_pn + 256;         // 2 x 128
        float* s_sim = s_pd + 256;         // 128
        int*   s_cnt = (int*)(s_sim + 128);// 2 x 128
        const int i = 96 + (blk - 48);
        #pragma unroll
        for (int q = 0; q < 16; q++) {
            int idx = t + q * 256; int r = idx >> 5, c4 = idx & 31;
            *(float4*)(es + r * LDS_ + c4 * 4) =
                *(const float4*)(emb + (size_t)r * 128 + c4 * 4);
        }
        __syncthreads();
        const int j = t & 127, half = t >> 7;
        const float* ei = es + i * LDS_;
        const float* ej = es + j * LDS_;
        float d = 0.f, nn = 0.f;
        #pragma unroll 8
        for (int q = 0; q < 16; q++) {
            int f4 = half * 16 + q;
            float4 b = *(const float4*)(ej + f4 * 4);
            float4 a = *(const float4*)(ei + f4 * 4);
            d  += a.x * b.x + a.y * b.y + a.z * b.z + a.w * b.w;
            nn += b.x * b.x + b.y * b.y + b.z * b.z + b.w * b.w;
        }
        s_pn[half * 128 + j] = nn;
        s_pd[half * 128 + j] = d;
        __syncthreads();
        if (half == 0) s_pn[j] = s_pn[j] + s_pn[128 + j];
        __syncthreads();
        if (half == 0) {
            float dij = s_pd[j] + s_pd[128 + j];
            s_sim[j] = dij / (sqrtf(s_pn[i]) * sqrtf(s_pn[j]));
        }
        __syncthreads();
        {
            float sim = s_sim[j];
            const float4* S = (const float4*)(s_sim + half * 64);
            int cnt = 0;
            #pragma unroll 8
            for (int q = 0; q < 16; q++) {
                float4 a = S[q];
                int base = half * 64 + q * 4;
                cnt += (a.x > sim) || (a.x == sim && base + 0 < j);
                cnt += (a.y > sim) || (a.y == sim && base + 1 < j);
                cnt += (a.z > sim) || (a.z == sim && base + 2 < j);
                cnt += (a.w > sim) || (a.w == sim && base + 3 < j);
            }
            s_cnt[half * 128 + j] = cnt;
        }
        __syncthreads();
        if (half == 0) {
            int c = s_cnt[j] + s_cnt[128 + j];
            out[65536 + i * 128 + j] = (c < kp[0]) ? 1.0f : 0.0f;
        }
    } else if (blk < 112) {
        // h0 tile [32 x 64]: h0 = x @ fp_W + fp_b, K=128
        int tt = blk - 80;
        int m0 = (tt >> 1) * 32, n0 = (tt & 1) * 64;
        float* As = sm;               // 32 x LDS_
        float* Bs = sm + 32 * LDS_;   // 64 x LDS_
        #pragma unroll
        for (int i = 0; i < 4; i++) {
            int idx = t + i * 256; int r = idx >> 5, c4 = idx & 31;
            *(float4*)(As + r * LDS_ + c4 * 4) =
                *(const float4*)(x + (size_t)(m0 + r) * 128 + c4 * 4);
        }
        {
            int kk = t & 127, half = t >> 7;
            #pragma unroll
            for (int p4 = 0; p4 < 8; p4++) {
                float4 v = *(const float4*)(fpW + (size_t)kk * 128 + n0 + (half * 8 + p4) * 4);
                Bs[((half * 8 + p4) * 4 + 0) * LDS_ + kk] = v.x;
                Bs[((half * 8 + p4) * 4 + 1) * LDS_ + kk] = v.y;
                Bs[((half * 8 + p4) * 4 + 2) * LDS_ + kk] = v.z;
                Bs[((half * 8 + p4) * 4 + 3) * LDS_ + kk] = v.w;
            }
        }
        __syncthreads();
        u64 acc[4][2];
        #pragma unroll
        for (int i = 0; i < 4; i++) { acc[i][0] = 0ull; acc[i][1] = 0ull; }
        wtile4(As + (size_t)(w * 4) * LDS_, Bs, lane, acc);
        #pragma unroll
        for (int i = 0; i < 4; i++) {
            int m = m0 + w * 4 + i;
            #pragma unroll
            for (int j = 0; j < 2; j++) {
                int n = n0 + lane + 32 * j;
                g_h0[(size_t)m * 128 + n] = f2lo(acc[i][j]) + f2hi(acc[i][j]) + fpb[n];
            }
        }
        __threadfence();
        __syncthreads();
        if (t == 0) atomicAdd(&g_c_h0, 1u);
    } else {
        // opW transpose: k-slice [(blk-112)*32, +32); thread = (n, half)
        int k0 = (blk - 112) * 32;
        int n = t & 127, half = t >> 7;
        float v[16];
        #pragma unroll
        for (int kk = 0; kk < 16; kk++)
            v[kk] = opW[(size_t)(k0 + half * 16 + kk) * 128 + n];
        #pragma unroll
        for (int q = 0; q < 4; q++)
            *(float4*)(g_opWt + (size_t)n * 512 + k0 + half * 16 + q * 4) =
                make_float4(v[q * 4], v[q * 4 + 1], v[q * 4 + 2], v[q * 4 + 3]);
        __threadfence();
        __syncthreads();
        if (t == 0) atomicAdd(&g_c_opw, 1u);
    }

    // ═ Wait: h0 ready (32 producer arrivals; overlapped with adj work) ══════
    if (t == 0) {
        while (*(volatile unsigned*)&g_c_h0 < 32u * (E + 1u)) { }
    }
    __syncthreads();
    __threadfence();

    // ═ Phase 1: r tile [32 x 64] = relu(h0 @ gat_W^T), block = (m-group, c) ═
    {
        float* As = sm;               // 32 x LDS_
        float* Bs = sm + 32 * LDS_;   // 64 x LDS_
        const int m0 = (blk >> 3) * 32, c0 = (blk & 7) * 64;
        #pragma unroll
        for (int i = 0; i < 4; i++) {
            int idx = t + i * 256; int r = idx >> 5, c4 = idx & 31;
            *(float4*)(As + r * LDS_ + c4 * 4) =
                *(const float4*)(g_h0 + (size_t)(m0 + r) * 128 + c4 * 4);
        }
        #pragma unroll
        for (int i = 0; i < 8; i++) {
            int idx = t + i * 256; int r = idx >> 5, c4 = idx & 31;
            *(float4*)(Bs + r * LDS_ + c4 * 4) =
                *(const float4*)(gatW + (size_t)(c0 + r) * 128 + c4 * 4);
        }
        __syncthreads();
        u64 acc[4][2];
        #pragma unroll
        for (int i = 0; i < 4; i++) { acc[i][0] = 0ull; acc[i][1] = 0ull; }
        wtile4(As + (size_t)(w * 4) * LDS_, Bs, lane, acc);
        #pragma unroll
        for (int i = 0; i < 4; i++) {
            int m = m0 + w * 4 + i;
            #pragma unroll
            for (int j = 0; j < 2; j++) {
                int c = c0 + lane + 32 * j;
                g_r[(size_t)m * 512 + c] = fmaxf(f2lo(acc[i][j]) + f2hi(acc[i][j]), 0.0f);
            }
        }
        __threadfence();
        __syncthreads();
        if (t == 0) *(volatile unsigned*)&g_flagr[blk] = E + 1u;   // no atomic: own slot
    }

    // ═ Wait: all 128 r tiles + opWt (flag array, syncthreads_and poll) ══════
    {
        int ok = (t < NBLK) ? (int)(*(volatile unsigned*)&g_flagr[t] >= E + 1u)
                            : (int)(*(volatile unsigned*)&g_c_opw >= 16u * (E + 1u));
        while (!__syncthreads_and(ok)) {
            ok = (t < NBLK) ? (int)(*(volatile unsigned*)&g_flagr[t] >= E + 1u)
                            : (int)(*(volatile unsigned*)&g_c_opw >= 16u * (E + 1u));
        }
        __threadfence();
    }

    // ═ Phase 2: out = x(1-mask) + (r @ op_W + op_b)·mask — tile [8m x 64n],
    //   4-way K-split across warp-pairs (group g owns K chunk g) ═════════════
    {
        float* As = sm;               // [4 chunks][8 rows][LDS_]
        float* Bs = sm + 32 * LDS_;   // [4 groups][64 rows][LDS_]
        float* red = sm;              // alias As after sync: 4*512 floats
        const int m0 = (blk >> 1) * 8, n0 = (blk & 1) * 64;
        const int g = w >> 1, wg = w & 1;

        #pragma unroll
        for (int i = 0; i < 4; i++) {
            int idx = t + i * 256;          // (m 0..7) x (kq 0..127 float4)
            int m = idx >> 7, kq = idx & 127;
            int c = kq >> 5, kl = kq & 31;
            *(float4*)(As + (size_t)(c * 8 + m) * LDS_ + kl * 4) =
                *(const float4*)(g_r + (size_t)(m0 + m) * 512 + kq * 4);
        }
        {
            int tp = wg * 32 + lane;        // 0..63 within pair
            #pragma unroll
            for (int h = 0; h < 32; h++) {
                int idx = tp + h * 64;      // (row 0..63) x (k4 0..31)
                int row = idx >> 5, k4 = idx & 31;
                *(float4*)(Bs + (size_t)(g * 64 + row) * LDS_ + k4 * 4) =
                    *(const float4*)(g_opWt + (size_t)(n0 + row) * 512 + g * 128 + k4 * 4);
            }
        }
        __syncthreads();
        u64 acc[4][2];
        #pragma unroll
        for (int i = 0; i < 4; i++) { acc[i][0] = 0ull; acc[i][1] = 0ull; }
        wtile4(As + (size_t)(g * 8 + wg * 4) * LDS_, Bs + (size_t)(g * 64) * LDS_, lane, acc);
        __syncthreads();
        #pragma unroll
        for (int i = 0; i < 4; i++)
            #pragma unroll
            for (int j = 0; j < 2; j++)
                red[g * 512 + (wg * 4 + i) * 64 + lane + 32 * j] =
                    f2lo(acc[i][j]) + f2hi(acc[i][j]);
        __syncthreads();
        #pragma unroll
        for (int q = 0; q < 2; q++) {
            int o = t + q * 256;            // 0..511
            int m = o >> 6, n = o & 63;
            float v = red[o] + red[512 + o] + red[1024 + o] + red[1536 + o] + opb[n0 + n];
            size_t gi = (size_t)(m0 + m) * 128 + n0 + n;
            float xv = x[gi], mv = mask[gi];
            out[gi] = xv * (1.0f - mv) + v * mv;
        }
    }

    if (blk == 0 && t == 0)
        *(volatile unsigned*)&g_epoch = E + 1u;   // all blocks read E long before this
}

extern "C" void kernel_launch(void* const* d_in, const int* in_sizes, int n_in,
                              void* d_out, int out_size)
{
    const float* x    = (const float*)d_in[0];
    const float* mask = (const float*)d_in[1];
    const float* emb  = (const float*)d_in[2];
    const float* gatW = (const float*)d_in[3];
    // d_in[4] = gat_a: provably unused (softmax over constant logits -> adj/k; rows sum to 1)
    const float* fpW  = (const float*)d_in[5];
    const float* fpb  = (const float*)d_in[6];
    const float* opW  = (const float*)d_in[7];
    const float* opb  = (const float*)d_in[8];
    const int*   kp   = (const int*)d_in[9];
    float* out = (float*)d_out;

    const int SMEM = (32 + 256) * LDS_ * 4;   // 152064 B (phase-2 layout is the max)
    cudaFuncSetAttribute(fused_kernel, cudaFuncAttributeMaxDynamicSharedMemorySize, SMEM);
    fused_kernel<<<NBLK, NTHR, SMEM>>>(x, mask, emb, gatW, fpW, fpb, opW, opb, kp, out);
}

// round 10
// speedup vs baseline: 1.4332x; 1.3249x over previous
#include <cuda_runtime.h>

#define NBLK 128
#define NTHR 256
#define LDS_ 132   // padded smem row stride (floats); 132 % 32 == 4 -> float4 lane-rows conflict-free
#define LDP2 516   // P2 row stride for K=512 buffers; 516 % 32 == 4 -> same class
typedef unsigned long long u64;

// Scratch (allocation-free rule: __device__ globals)
__device__ float g_h0[512 * 128];    // x @ fp_W + fp_b
__device__ float g_r[512 * 512];     // relu(h0 @ gat_W^T)
__device__ float g_opWt[128 * 512];  // op_W transposed: [n][k]
__device__ unsigned g_cnt = 0;       // barrier arrivals (returns to 0 every launch)
__device__ unsigned g_gen = 0;       // barrier generation (monotonic across launches — fine)

__device__ __forceinline__ void grid_barrier()
{
    __threadfence();
    __syncthreads();
    if (threadIdx.x == 0) {
        unsigned gen = *(volatile unsigned*)&g_gen;   // read BEFORE arriving
        unsigned t = atomicAdd(&g_cnt, 1u);
        if (t == NBLK - 1) {
            g_cnt = 0;
            __threadfence();
            atomicAdd(&g_gen, 1u);                    // release
        } else {
            while (*(volatile unsigned*)&g_gen == gen) { }
        }
    }
    __syncthreads();
}

__device__ __forceinline__ u64 ffma2(u64 a, u64 b, u64 c) {
    u64 d;
    asm("fma.rn.f32x2 %0, %1, %2, %3;" : "=l"(d) : "l"(a), "l"(b), "l"(c));
    return d;
}
__device__ __forceinline__ float f2lo(u64 v) { return __uint_as_float((unsigned)v); }
__device__ __forceinline__ float f2hi(u64 v) { return __uint_as_float((unsigned)(v >> 32)); }

// Warp tile 16m x 64n over NK4*4 k-values. A rows broadcast; B lane-strided.
template<int NK4, int LDA, int LDB>
__device__ __forceinline__ void wtile16m(const float* __restrict__ As,
                                         const float* __restrict__ Bs,
                                         int lane, u64 acc[16][2])
{
    #pragma unroll
    for (int k4 = 0; k4 < NK4; k4++) {
        ulonglong2 b0 = *(const ulonglong2*)(Bs + (size_t)lane        * LDB + k4 * 4);
        ulonglong2 b1 = *(const ulonglong2*)(Bs + (size_t)(lane + 32) * LDB + k4 * 4);
        #pragma unroll
        for (int i = 0; i < 16; i++) {
            ulonglong2 a = *(const ulonglong2*)(As + (size_t)i * LDA + k4 * 4);
            acc[i][0] = ffma2(a.x, b0.x, acc[i][0]);
            acc[i][0] = ffma2(a.y, b0.y, acc[i][0]);
            acc[i][1] = ffma2(a.x, b1.x, acc[i][1]);
            acc[i][1] = ffma2(a.y, b1.y, acc[i][1]);
        }
    }
}

// Warp tile 8m x 64n over NK4*4 k-values.
template<int NK4, int LDA, int LDB>
__device__ __forceinline__ void wtile8m(const float* __restrict__ As,
                                        const float* __restrict__ Bs,
                                        int lane, u64 acc[8][2])
{
    #pragma unroll
    for (int k4 = 0; k4 < NK4; k4++) {
        ulonglong2 b0 = *(const ulonglong2*)(Bs + (size_t)lane        * LDB + k4 * 4);
        ulonglong2 b1 = *(const ulonglong2*)(Bs + (size_t)(lane + 32) * LDB + k4 * 4);
        #pragma unroll
        for (int i = 0; i < 8; i++) {
            ulonglong2 a = *(const ulonglong2*)(As + (size_t)i * LDA + k4 * 4);
            acc[i][0] = ffma2(a.x, b0.x, acc[i][0]);
            acc[i][0] = ffma2(a.y, b0.y, acc[i][0]);
            acc[i][1] = ffma2(a.x, b1.x, acc[i][1]);
            acc[i][1] = ffma2(a.y, b1.y, acc[i][1]);
        }
    }
}

// 32m x 64n GEMM over K=128 with 4-way K-split across warp pairs + smem reduce.
// Caller must have loaded Bs (sm + 32*LDS_, 64 rows x LDS_) BEFORE calling (sync inside).
// EPI 0: += bias[n] (h0).  EPI 1: relu (r).
template<int EPI>
__device__ __forceinline__ void gemm_32x64(float* sm, const float* __restrict__ Agm, int m0,
                                           const float* __restrict__ bias,
                                           float* __restrict__ Cgm, int ldC, int c0,
                                           int t, int lane, int w)
{
    float* As = sm;                    // 32 x LDS_
    float* Pb = sm + 96 * LDS_;        // 8 buffers x 1040 (each 16x64 floats)
    #pragma unroll
    for (int i = 0; i < 4; i++) {
        int idx = t + i * 256; int row = idx >> 5, c4 = idx & 31;
        *(float4*)(As + row * LDS_ + c4 * 4) =
            *(const float4*)(Agm + (size_t)(m0 + row) * 128 + c4 * 4);
    }
    __syncthreads();
    const int mh = w & 1, kq = w >> 1;
    u64 acc[16][2];
    #pragma unroll
    for (int i = 0; i < 16; i++) { acc[i][0] = 0ull; acc[i][1] = 0ull; }
    wtile16m<8, LDS_, LDS_>(As + (size_t)(mh * 16) * LDS_ + kq * 32,
                            sm + 32 * LDS_ + kq * 32, lane, acc);
    float* P = Pb + w * 1040;
    #pragma unroll
    for (int i = 0; i < 16; i++)
        #pragma unroll
        for (int j = 0; j < 2; j++)
            P[i * 64 + lane + 32 * j] = f2lo(acc[i][j]) + f2hi(acc[i][j]);
    __syncthreads();
    // reduce 4 k-partials per m-half; 512 float4s total, 2 per thread
    #pragma unroll
    for (int q = 0; q < 2; q++) {
        int id = t + q * 256;            // 0..511
        int mh2 = id >> 8, e4 = id & 255;
        int i = e4 >> 4, n4 = (e4 & 15) * 4;
        float4 v = *(const float4*)(Pb + (size_t)mh2 * 1040 + i * 64 + n4);
        #pragma unroll
        for (int kk = 1; kk < 4; kk++) {
            float4 p = *(const float4*)(Pb + (size_t)(2 * kk + mh2) * 1040 + i * 64 + n4);
            v.x += p.x; v.y += p.y; v.z += p.z; v.w += p.w;
        }
        if (EPI == 0) {
            float4 b = *(const float4*)(bias + n4);
            v.x += b.x; v.y += b.y; v.z += b.z; v.w += b.w;
        }
        if (EPI == 1) {
            v.x = fmaxf(v.x, 0.f); v.y = fmaxf(v.y, 0.f);
            v.z = fmaxf(v.z, 0.f); v.w = fmaxf(v.w, 0.f);
        }
        *(float4*)(Cgm + (size_t)(m0 + mh2 * 16 + i) * ldC + c0 + n4) = v;
    }
}

__global__ void __launch_bounds__(NTHR, 1)
fused_kernel(const float* __restrict__ x,   const float* __restrict__ mask,
             const float* __restrict__ emb, const float* __restrict__ gatW,
             const float* __restrict__ fpW, const float* __restrict__ fpb,
             const float* __restrict__ opW, const float* __restrict__ opb,
             const int*   __restrict__ kp,  float* __restrict__ out)
{
    extern __shared__ float sm[];
    const int blk = blockIdx.x, t = threadIdx.x, lane = t & 31, w = t >> 5;

    // ═ Phase 0: adj 2-row (0..47) ∥ adj 1-row (48..79) ∥ h0 (80..111) ∥ opWt (112..127)
    if (blk < 48) {
        float* es    = sm;                 // 128 x LDS_
        float* s_n2  = sm + 128 * LDS_;    // 128
        float* s_sim = s_n2 + 128;         // 2 x 128
        #pragma unroll
        for (int i = 0; i < 16; i++) {
            int idx = t + i * 256; int r = idx >> 5, c4 = idx & 31;
            *(float4*)(es + r * LDS_ + c4 * 4) =
                *(const float4*)(emb + (size_t)r * 128 + c4 * 4);
        }
        __syncthreads();
        const int rr = t >> 7, j = t & 127;
        const int irow = blk * 2 + rr;
        const float* ei = es + irow * LDS_;
        const float* ej = es + j * LDS_;
        float dij = 0.f, nj = 0.f;
        #pragma unroll 8
        for (int f4 = 0; f4 < 32; f4++) {
            float4 b = *(const float4*)(ej + f4 * 4);
            float4 a = *(const float4*)(ei + f4 * 4);
            dij += a.x * b.x + a.y * b.y + a.z * b.z + a.w * b.w;
            nj  += b.x * b.x + b.y * b.y + b.z * b.z + b.w * b.w;
        }
        if (rr == 0) s_n2[j] = nj;
        __syncthreads();
        float sim = dij / (sqrtf(s_n2[irow]) * sqrtf(nj));
        s_sim[rr * 128 + j] = sim;
        __syncthreads();
        const float4* S = (const float4*)(s_sim + rr * 128);
        int cnt = 0;
        #pragma unroll 8
        for (int q = 0; q < 32; q++) {
            float4 a = S[q];
            int base = q * 4;
            cnt += (a.x > sim) || (a.x == sim && base + 0 < j);
            cnt += (a.y > sim) || (a.y == sim && base + 1 < j);
            cnt += (a.z > sim) || (a.z == sim && base + 2 < j);
            cnt += (a.w > sim) || (a.w == sim && base + 3 < j);
        }
        out[65536 + irow * 128 + j] = (cnt < kp[0]) ? 1.0f : 0.0f;
    } else if (blk < 80) {
        // single row i = 96 + (blk-48); dot and rank split across thread halves
        float* es    = sm;                 // 128 x LDS_
        float* s_pn  = sm + 128 * LDS_;    // 2 x 128
        float* s_pd  = s_pn + 256;         // 2 x 128
        float* s_sim = s_pd + 256;         // 128
        int*   s_cnt = (int*)(s_sim + 128);// 2 x 128
        const int i = 96 + (blk - 48);
        #pragma unroll
        for (int q = 0; q < 16; q++) {
            int idx = t + q * 256; int r = idx >> 5, c4 = idx & 31;
            *(float4*)(es + r * LDS_ + c4 * 4) =
                *(const float4*)(emb + (size_t)r * 128 + c4 * 4);
        }
        __syncthreads();
        const int j = t & 127, half = t >> 7;
        const float* ei = es + i * LDS_;
        const float* ej = es + j * LDS_;
        float d = 0.f, nn = 0.f;
        #pragma unroll 8
        for (int q = 0; q < 16; q++) {
            int f4 = half * 16 + q;
            float4 b = *(const float4*)(ej + f4 * 4);
            float4 a = *(const float4*)(ei + f4 * 4);
            d  += a.x * b.x + a.y * b.y + a.z * b.z + a.w * b.w;
            nn += b.x * b.x + b.y * b.y + b.z * b.z + b.w * b.w;
        }
        s_pn[half * 128 + j] = nn;
        s_pd[half * 128 + j] = d;
        __syncthreads();
        if (half == 0) s_pn[j] = s_pn[j] + s_pn[128 + j];
        __syncthreads();
        if (half == 0) {
            float dij = s_pd[j] + s_pd[128 + j];
            s_sim[j] = dij / (sqrtf(s_pn[i]) * sqrtf(s_pn[j]));
        }
        __syncthreads();
        {
            float sim = s_sim[j];
            const float4* S = (const float4*)(s_sim + half * 64);
            int cnt = 0;
            #pragma unroll 8
            for (int q = 0; q < 16; q++) {
                float4 a = S[q];
                int base = half * 64 + q * 4;
                cnt += (a.x > sim) || (a.x == sim && base + 0 < j);
                cnt += (a.y > sim) || (a.y == sim && base + 1 < j);
                cnt += (a.z > sim) || (a.z == sim && base + 2 < j);
                cnt += (a.w > sim) || (a.w == sim && base + 3 < j);
            }
            s_cnt[half * 128 + j] = cnt;
        }
        __syncthreads();
        if (half == 0) {
            int c = s_cnt[j] + s_cnt[128 + j];
            out[65536 + i * 128 + j] = (c < kp[0]) ? 1.0f : 0.0f;
        }
    } else if (blk < 112) {
        // h0 tile [32m x 64n] = x @ fp_W + fp_b, K=128 (m16n64 warps, 4-way K-split)
        int tt = blk - 80;
        int m0 = (tt >> 1) * 32, n0 = (tt & 1) * 64;
        float* Bs = sm + 32 * LDS_;   // 64 x LDS_ (row = n_local, col = k)
        {   // transpose fp_W cols [n0, n0+64): thread (kk, half) owns k-row kk
            int kk = t & 127, half = t >> 7;
            #pragma unroll
            for (int p4 = 0; p4 < 8; p4++) {
                float4 v = *(const float4*)(fpW + (size_t)kk * 128 + n0 + (half * 8 + p4) * 4);
                Bs[((half * 8 + p4) * 4 + 0) * LDS_ + kk] = v.x;
                Bs[((half * 8 + p4) * 4 + 1) * LDS_ + kk] = v.y;
                Bs[((half * 8 + p4) * 4 + 2) * LDS_ + kk] = v.z;
                Bs[((half * 8 + p4) * 4 + 3) * LDS_ + kk] = v.w;
            }
        }
        gemm_32x64<0>(sm, x, m0, fpb + n0, g_h0, 128, n0, t, lane, w);
    } else {
        // opW transpose: k-slice [(blk-112)*32, +32); thread = (n, half)
        int k0 = (blk - 112) * 32;
        int n = t & 127, half = t >> 7;
        float v[16];
        #pragma unroll
        for (int kk = 0; kk < 16; kk++)
            v[kk] = opW[(size_t)(k0 + half * 16 + kk) * 128 + n];
        #pragma unroll
        for (int q = 0; q < 4; q++)
            *(float4*)(g_opWt + (size_t)n * 512 + k0 + half * 16 + q * 4) =
                make_float4(v[q * 4], v[q * 4 + 1], v[q * 4 + 2], v[q * 4 + 3]);
    }
    grid_barrier();

    // ═ Phase 1: r tile [32m x 64c] = relu(h0 @ gat_W^T), block = (m-group, c) ═
    {
        const int m0 = (blk >> 3) * 32, c0 = (blk & 7) * 64;
        float* Bs = sm + 32 * LDS_;   // gatW rows c0..c0+64, K-major: direct copy
        #pragma unroll
        for (int i = 0; i < 8; i++) {
            int idx = t + i * 256; int r = idx >> 5, c4 = idx & 31;
            *(float4*)(Bs + r * LDS_ + c4 * 4) =
                *(const float4*)(gatW + (size_t)(c0 + r) * 128 + c4 * 4);
        }
        gemm_32x64<1>(sm, g_h0, m0, nullptr, g_r, 512, c0, t, lane, w);
    }
    grid_barrier();

    // ═ Phase 2: out = x(1-mask) + (r @ op_W + op_b)·mask — tile [8m x 64n],
    //   8-way K-split: warp w owns k in [64w, 64w+64); warp-local loads ═══════
    {
        float* As = sm;                        // 8 x LDP2
        float* Bs = sm + 8 * LDP2;             // 64 x LDP2
        float* Pb = sm + 8 * LDP2 + 64 * LDP2; // 8 x 520
        const int m0 = (blk >> 1) * 8, n0 = (blk & 1) * 64;

        // warp-local As slice: rows 0..7, k in [64w, 64w+64)
        #pragma unroll
        for (int i = 0; i < 4; i++) {
            int idx = lane + 32 * i;           // 0..127 over (row 0..7) x (c4 0..15)
            int row = idx >> 4, c4 = idx & 15;
            *(float4*)(As + (size_t)row * LDP2 + w * 64 + c4 * 4) =
                *(const float4*)(g_r + (size_t)(m0 + row) * 512 + w * 64 + c4 * 4);
        }
        // warp-local Bs slice: rows 0..63, k in [64w, 64w+64)
        #pragma unroll
        for (int i = 0; i < 32; i++) {
            int idx = lane + 32 * i;           // 0..1023 over (row 0..63) x (c4 0..15)
            int row = idx >> 4, c4 = idx & 15;
            *(float4*)(Bs + (size_t)row * LDP2 + w * 64 + c4 * 4) =
                *(const float4*)(g_opWt + (size_t)(n0 + row) * 512 + w * 64 + c4 * 4);
        }
        __syncwarp();
        u64 acc[8][2];
        #pragma unroll
        for (int i = 0; i < 8; i++) { acc[i][0] = 0ull; acc[i][1] = 0ull; }
        wtile8m<16, LDP2, LDP2>(As + w * 64, Bs + w * 64, lane, acc);
        float* P = Pb + w * 520;
        #pragma unroll
        for (int i = 0; i < 8; i++)
            #pragma unroll
            for (int j = 0; j < 2; j++)
                P[i * 64 + lane + 32 * j] = f2lo(acc[i][j]) + f2hi(acc[i][j]);
        __syncthreads();
        // reduce 8 partials; 512 outputs, 2 per thread (float2)
        {
            int o = t * 2;                     // 0..510
            int m = o >> 6, n = o & 63;
            float v0 = 0.f, v1 = 0.f;
            #pragma unroll
            for (int ww = 0; ww < 8; ww++) {
                const float* p = Pb + (size_t)ww * 520 + o;
                v0 += p[0]; v1 += p[1];
            }
            v0 += opb[n0 + n]; v1 += opb[n0 + n + 1];
            size_t gi = (size_t)(m0 + m) * 128 + n0 + n;
            float2 xv = *(const float2*)(x + gi);
            float2 mv = *(const float2*)(mask + gi);
            float2 ov;
            ov.x = xv.x * (1.0f - mv.x) + v0 * mv.x;
            ov.y = xv.y * (1.0f - mv.y) + v1 * mv.y;
            *(float2*)(out + gi) = ov;
        }
    }
}

extern "C" void kernel_launch(void* const* d_in, const int* in_sizes, int n_in,
                              void* d_out, int out_size)
{
    const float* x    = (const float*)d_in[0];
    const float* mask = (const float*)d_in[1];
    const float* emb  = (const float*)d_in[2];
    const float* gatW = (const float*)d_in[3];
    // d_in[4] = gat_a: provably unused (softmax over constant logits -> adj/k; rows sum to 1)
    const float* fpW  = (const float*)d_in[5];
    const float* fpb  = (const float*)d_in[6];
    const float* opW  = (const float*)d_in[7];
    const float* opb  = (const float*)d_in[8];
    const int*   kp   = (const int*)d_in[9];
    float* out = (float*)d_out;

    // max over phases: P2 = (72 * LDP2 + 8 * 520) floats = 41312 floats = 165248 B
    const int SMEM = (72 * LDP2 + 8 * 520) * 4;
    cudaFuncSetAttribute(fused_kernel, cudaFuncAttributeMaxDynamicSharedMemorySize, SMEM);
    fused_kernel<<<NBLK, NTHR, SMEM>>>(x, mask, emb, gatW, fpW, fpb, opW, opb, kp, out);
}